// round 3
// baseline (speedup 1.0000x reference)
#include <cuda_runtime.h>
#include <math.h>

#define LQ 1024
#define PK 4096
#define DM 512
#define NH 8
#define DH 64
#define NR 50

// ---------------- scratch (device globals; no allocations allowed) ----------
__device__ float g_Qp[LQ * DM];            // 2 MB
__device__ float g_Kp[PK * DM];            // 8 MB
__device__ float g_Vp[PK * DM];            // 8 MB
__device__ float g_S[NH * LQ * PK];        // 134 MB  logits -> exp(logits), layout [H][L][P]
__device__ float g_rZ[LQ * NH];            // 1/Z per (l,h)
__device__ float g_O[LQ * DM];             // attention output (pre out-proj)
__device__ float g_Xo[LQ * DM];            // out-proj result

// ---------------------------------------------------------------------------
// Generic NT SGEMM: C[m,n] = alpha * sum_k A[m*lda+k] * B[n*ldb+k] (+ bias[n])
// 128x128 tile, BK=8, 256 threads, 8x8 microtile. M,N multiples of 128,
// K multiple of 8 (all guaranteed by problem shapes).
// blockIdx.z = batch; per-batch element offsets aStride/bStride/cStride.
// ---------------------------------------------------------------------------
__global__ __launch_bounds__(256) void sgemm_nt(
    const float* __restrict__ A, int lda, int aStride,
    const float* __restrict__ B, int ldb, int bStride,
    float* __restrict__ C, int ldc, long cStride,
    int K, float alpha, const float* __restrict__ bias)
{
    __shared__ float As[8][132];
    __shared__ float Bs[8][132];

    const int bz = blockIdx.z;
    const float* Ab = A + (long)bz * aStride;
    const float* Bb = B + (long)bz * bStride;
    float* Cb = C + (long)bz * cStride;

    const int m0 = blockIdx.y * 128;
    const int n0 = blockIdx.x * 128;
    const int t  = threadIdx.x;
    const int tx = t & 15;
    const int ty = t >> 4;
    const int lrow = t >> 1;
    const int lk   = (t & 1) * 4;

    float acc[8][8];
#pragma unroll
    for (int i = 0; i < 8; i++)
#pragma unroll
        for (int j = 0; j < 8; j++) acc[i][j] = 0.0f;

    const float* aPtr = Ab + (long)(m0 + lrow) * lda + lk;
    const float* bPtr = Bb + (long)(n0 + lrow) * ldb + lk;

    for (int k0 = 0; k0 < K; k0 += 8) {
        float4 av = *(const float4*)(aPtr + k0);
        float4 bv = *(const float4*)(bPtr + k0);
        As[lk + 0][lrow] = av.x; As[lk + 1][lrow] = av.y;
        As[lk + 2][lrow] = av.z; As[lk + 3][lrow] = av.w;
        Bs[lk + 0][lrow] = bv.x; Bs[lk + 1][lrow] = bv.y;
        Bs[lk + 2][lrow] = bv.z; Bs[lk + 3][lrow] = bv.w;
        __syncthreads();

#pragma unroll
        for (int kk = 0; kk < 8; kk++) {
            float4 a0 = *(const float4*)&As[kk][ty * 8];
            float4 a1 = *(const float4*)&As[kk][ty * 8 + 4];
            float4 b0 = *(const float4*)&Bs[kk][tx * 8];
            float4 b1 = *(const float4*)&Bs[kk][tx * 8 + 4];
            float ar[8] = {a0.x, a0.y, a0.z, a0.w, a1.x, a1.y, a1.z, a1.w};
            float br_[8] = {b0.x, b0.y, b0.z, b0.w, b1.x, b1.y, b1.z, b1.w};
#pragma unroll
            for (int i = 0; i < 8; i++)
#pragma unroll
                for (int j = 0; j < 8; j++)
                    acc[i][j] = fmaf(ar[i], br_[j], acc[i][j]);
        }
        __syncthreads();
    }

    float bb[8];
#pragma unroll
    for (int j = 0; j < 8; j++) bb[j] = bias ? bias[n0 + tx * 8 + j] : 0.0f;

#pragma unroll
    for (int i = 0; i < 8; i++) {
        float* crow = Cb + (long)(m0 + ty * 8 + i) * ldc + n0 + tx * 8;
        float4 o0 = make_float4(fmaf(alpha, acc[i][0], bb[0]),
                                fmaf(alpha, acc[i][1], bb[1]),
                                fmaf(alpha, acc[i][2], bb[2]),
                                fmaf(alpha, acc[i][3], bb[3]));
        float4 o1 = make_float4(fmaf(alpha, acc[i][4], bb[4]),
                                fmaf(alpha, acc[i][5], bb[5]),
                                fmaf(alpha, acc[i][6], bb[6]),
                                fmaf(alpha, acc[i][7], bb[7]));
        *(float4*)crow       = o0;
        *(float4*)(crow + 4) = o1;
    }
}

// ---------------------------------------------------------------------------
// bias + exp + rowsum kernel. One block per query row l (1024 blocks).
// Streams cross_rbf[l, :, :] once, computes bias = rbf @ Wr^T + br, adds
// pre-computed scores, exponentiates IN PLACE in g_S, and produces
// rZ[l,h] = 1 / sum_p exp(logit). Warp w of the block owns head h=w,
// lanes own p%32 -> coalesced score/E access and conflict-free reduction.
// Safe without max-subtraction: |logit| < ~2 by construction.
// ---------------------------------------------------------------------------
__global__ __launch_bounds__(256) void bias_exp_kernel(
    const float* __restrict__ rbf, const float* __restrict__ Wr,
    const float* __restrict__ br, float* __restrict__ S,
    float* __restrict__ rZ)
{
    __shared__ float wr_s[NH * NR];   // 400
    __shared__ float br_s[NH];
    __shared__ float rbf_s[32 * NR];  // 1600

    const int l = blockIdx.x;
    const int t = threadIdx.x;
    // NH*NR = 400 > blockDim (256) -> strided loop, not a single
    // predicated load (heads 5-7 previously read garbage weights).
    for (int i = t; i < NH * NR; i += 256) wr_s[i] = Wr[i];
    if (t < NH) br_s[t] = br[t];
    __syncthreads();

    const int h  = t >> 5;   // warp id = head
    const int pp = t & 31;   // lane = p within tile
    const float bh = br_s[h];
    const float* wrow = &wr_s[h * NR];

    const float* rbf_l = rbf + (long)l * PK * NR;
    float* Sl = S + (long)h * ((long)LQ * PK) + (long)l * PK;

    float zacc = 0.0f;
    for (int p0 = 0; p0 < PK; p0 += 32) {
        __syncthreads();  // previous tile's compute done before overwrite
        for (int i = t; i < 32 * NR; i += 256)
            rbf_s[i] = rbf_l[(long)p0 * NR + i];
        __syncthreads();

        const float* rrow = &rbf_s[pp * NR];
        float bias = bh;
#pragma unroll
        for (int r = 0; r < NR; r++) bias = fmaf(wrow[r], rrow[r], bias);

        float logit = Sl[p0 + pp] + bias;
        float e = __expf(logit);
        Sl[p0 + pp] = e;
        zacc += e;
    }

#pragma unroll
    for (int o = 16; o > 0; o >>= 1)
        zacc += __shfl_xor_sync(0xFFFFFFFFu, zacc, o);
    if (pp == 0) rZ[l * NH + h] = 1.0f / zacc;
}

// ---------------------------------------------------------------------------
// attn @ V: per head h, O[l, h*64+d] = rZ[l,h] * sum_p E[h][l][p] * V[p, h*64+d]
// 128(l) x 64(d) tile, BK=16, 256 threads, 8x4 microtile.
// ---------------------------------------------------------------------------
__global__ __launch_bounds__(256) void attnv_kernel(
    const float* __restrict__ E, const float* __restrict__ V,
    const float* __restrict__ rZ, float* __restrict__ O)
{
    __shared__ float As[16][132];
    __shared__ float Bs[16][64];

    const int h  = blockIdx.y;
    const int m0 = blockIdx.x * 128;
    const float* Eh = E + (long)h * ((long)LQ * PK);

    const int t  = threadIdx.x;
    const int tx = t & 15;
    const int ty = t >> 4;
    const int arow = t >> 1;
    const int ak   = (t & 1) * 8;
    const int bk   = t >> 4;
    const int bf   = t & 15;

    float acc[8][4];
#pragma unroll
    for (int i = 0; i < 8; i++)
#pragma unroll
        for (int j = 0; j < 4; j++) acc[i][j] = 0.0f;

    const float* aPtr = Eh + (long)(m0 + arow) * PK + ak;
    const float* bPtr = V + (long)bk * DM + h * DH + bf * 4;

    for (int k0 = 0; k0 < PK; k0 += 16) {
        float4 a0 = *(const float4*)(aPtr + k0);
        float4 a1 = *(const float4*)(aPtr + k0 + 4);
        float4 bv = *(const float4*)(bPtr + (long)k0 * DM);
        As[ak + 0][arow] = a0.x; As[ak + 1][arow] = a0.y;
        As[ak + 2][arow] = a0.z; As[ak + 3][arow] = a0.w;
        As[ak + 4][arow] = a1.x; As[ak + 5][arow] = a1.y;
        As[ak + 6][arow] = a1.z; As[ak + 7][arow] = a1.w;
        *(float4*)&Bs[bk][bf * 4] = bv;
        __syncthreads();

#pragma unroll
        for (int kk = 0; kk < 16; kk++) {
            float4 a0v = *(const float4*)&As[kk][ty * 8];
            float4 a1v = *(const float4*)&As[kk][ty * 8 + 4];
            float4 b   = *(const float4*)&Bs[kk][tx * 4];
            float ar[8] = {a0v.x, a0v.y, a0v.z, a0v.w, a1v.x, a1v.y, a1v.z, a1v.w};
            float br_[4] = {b.x, b.y, b.z, b.w};
#pragma unroll
            for (int i = 0; i < 8; i++)
#pragma unroll
                for (int j = 0; j < 4; j++)
                    acc[i][j] = fmaf(ar[i], br_[j], acc[i][j]);
        }
        __syncthreads();
    }

#pragma unroll
    for (int i = 0; i < 8; i++) {
        int m = m0 + ty * 8 + i;
        float sc = rZ[m * NH + h];
        float4 o = make_float4(acc[i][0] * sc, acc[i][1] * sc,
                               acc[i][2] * sc, acc[i][3] * sc);
        *(float4*)(O + (long)m * DM + h * DH + tx * 4) = o;
    }
}

// ---------------------------------------------------------------------------
// attn_mean[l,p] = (1/8) * sum_h E[h][l][p] * rZ[l,h]
// One block handles 256 consecutive p of one l. P/256 = 16 blocks per l.
// ---------------------------------------------------------------------------
__global__ __launch_bounds__(256) void attn_mean_kernel(
    const float* __restrict__ E, const float* __restrict__ rZ,
    float* __restrict__ out)
{
    __shared__ float rz[NH];
    const int l = blockIdx.x >> 4;
    const int p = ((blockIdx.x & 15) << 8) + threadIdx.x;
    if (threadIdx.x < NH) rz[threadIdx.x] = rZ[l * NH + threadIdx.x];
    __syncthreads();

    const float* El = E + (long)l * PK + p;
    float s = 0.0f;
#pragma unroll
    for (int h = 0; h < NH; h++)
        s = fmaf(El[(long)h * ((long)LQ * PK)], rz[h], s);
    out[(long)l * PK + p] = s * 0.125f;
}

// ---------------------------------------------------------------------------
// LayerNorm(query + Xo) * gamma + beta. One block per row, 256 threads,
// 2 elements per thread.
// ---------------------------------------------------------------------------
__global__ __launch_bounds__(256) void ln_kernel(
    const float* __restrict__ query, const float* __restrict__ Xo,
    const float* __restrict__ gamma, const float* __restrict__ beta,
    float* __restrict__ y)
{
    __shared__ float rs[8], rq[8];
    const int l = blockIdx.x;
    const int t = threadIdx.x;
    const int lane = t & 31, warp = t >> 5;

    float2 q  = *(const float2*)(query + (long)l * DM + t * 2);
    float2 xo = *(const float2*)(Xo    + (long)l * DM + t * 2);
    float x0 = q.x + xo.x;
    float x1 = q.y + xo.y;

    float s  = x0 + x1;
    float sq = x0 * x0 + x1 * x1;
#pragma unroll
    for (int o = 16; o > 0; o >>= 1) {
        s  += __shfl_xor_sync(0xFFFFFFFFu, s, o);
        sq += __shfl_xor_sync(0xFFFFFFFFu, sq, o);
    }
    if (lane == 0) { rs[warp] = s; rq[warp] = sq; }
    __syncthreads();
    if (warp == 0) {
        float a = (lane < 8) ? rs[lane] : 0.0f;
        float b = (lane < 8) ? rq[lane] : 0.0f;
#pragma unroll
        for (int o = 4; o > 0; o >>= 1) {
            a += __shfl_xor_sync(0xFFFFFFFFu, a, o);
            b += __shfl_xor_sync(0xFFFFFFFFu, b, o);
        }
        if (lane == 0) { rs[0] = a; rq[0] = b; }
    }
    __syncthreads();

    const float mean = rs[0] * (1.0f / DM);
    const float var  = rq[0] * (1.0f / DM) - mean * mean;
    const float rstd = rsqrtf(var + 1e-5f);

    float2 g = *(const float2*)(gamma + t * 2);
    float2 b = *(const float2*)(beta + t * 2);
    float2 o;
    o.x = (x0 - mean) * rstd * g.x + b.x;
    o.y = (x1 - mean) * rstd * g.y + b.y;
    *(float2*)(y + (long)l * DM + t * 2) = o;
}

// ---------------------------------------------------------------------------
extern "C" void kernel_launch(void* const* d_in, const int* in_sizes, int n_in,
                              void* d_out, int out_size)
{
    const float* query = (const float*)d_in[0];
    const float* key   = (const float*)d_in[1];
    const float* value = (const float*)d_in[2];
    const float* rbf   = (const float*)d_in[3];
    const float* Wq = (const float*)d_in[4];
    const float* bq = (const float*)d_in[5];
    const float* Wk = (const float*)d_in[6];
    const float* bk = (const float*)d_in[7];
    const float* Wv = (const float*)d_in[8];
    const float* bv = (const float*)d_in[9];
    const float* Wr = (const float*)d_in[10];
    const float* br = (const float*)d_in[11];
    const float* Wo = (const float*)d_in[12];
    const float* bo = (const float*)d_in[13];
    const float* gamma = (const float*)d_in[14];
    const float* beta  = (const float*)d_in[15];
    float* out = (float*)d_out;

    float *Qp, *Kp, *Vp, *S, *rZ, *O, *Xo;
    cudaGetSymbolAddress((void**)&Qp, g_Qp);
    cudaGetSymbolAddress((void**)&Kp, g_Kp);
    cudaGetSymbolAddress((void**)&Vp, g_Vp);
    cudaGetSymbolAddress((void**)&S,  g_S);
    cudaGetSymbolAddress((void**)&rZ, g_rZ);
    cudaGetSymbolAddress((void**)&O,  g_O);
    cudaGetSymbolAddress((void**)&Xo, g_Xo);

    // Projections: X @ W^T + b  (NT gemm, K=512)
    sgemm_nt<<<dim3(DM / 128, LQ / 128, 1), 256>>>(query, DM, 0, Wq, DM, 0,
                                                   Qp, DM, 0, DM, 1.0f, bq);
    sgemm_nt<<<dim3(DM / 128, PK / 128, 1), 256>>>(key, DM, 0, Wk, DM, 0,
                                                   Kp, DM, 0, DM, 1.0f, bk);
    sgemm_nt<<<dim3(DM / 128, PK / 128, 1), 256>>>(value, DM, 0, Wv, DM, 0,
                                                   Vp, DM, 0, DM, 1.0f, bv);

    // Scores: per head, S[h][l][p] = 0.125 * Q_h[l,:] . K_h[p,:]
    sgemm_nt<<<dim3(PK / 128, LQ / 128, NH), 256>>>(Qp, DM, DH, Kp, DM, DH,
                                                    S, PK, (long)LQ * PK,
                                                    DH, 0.125f, nullptr);

    // bias from cross_rbf + exp + per-(l,h) denominator
    bias_exp_kernel<<<LQ, 256>>>(rbf, Wr, br, S, rZ);

    // attn @ V with 1/Z scaling
    attnv_kernel<<<dim3(LQ / 128, NH), 256>>>(S, Vp, rZ, O);

    // attn.mean over heads -> second output
    attn_mean_kernel<<<LQ * (PK / 256), 256>>>(S, rZ, out + (long)LQ * DM);

    // output projection
    sgemm_nt<<<dim3(DM / 128, LQ / 128, 1), 256>>>(O, DM, 0, Wo, DM, 0,
                                                   Xo, DM, 0, DM, 1.0f, bo);

    // residual + layernorm -> first output
    ln_kernel<<<LQ, 256>>>(query, Xo, gamma, beta, out);
}

// round 6
// speedup vs baseline: 1.2519x; 1.2519x over previous
#include <cuda_runtime.h>
#include <math.h>

#define LQ 1024
#define PK 4096
#define DM 512
#define NH 8
#define DH 64
#define NR 50
#define TPB 128            // p-tile for bias_exp_v2
#define SPLIT 8            // split-K factor for attnv
#define CHUNK (PK / SPLIT) // 512

// ---------------- scratch (device globals; no allocations allowed) ----------
__device__ float g_Qp[LQ * DM];            // 2 MB
__device__ float g_Kp[PK * DM];            // 8 MB
__device__ float g_Vp[PK * DM];            // 8 MB
__device__ float g_S[NH * LQ * PK];        // 134 MB  logits -> exp(logits), [H][L][P]
__device__ float g_rZ[LQ * NH];            // 1/Z per (l,h)
__device__ float g_O[LQ * DM];             // attention output (pre out-proj)
__device__ float g_Op[SPLIT * LQ * DM];    // 16 MB   split-K partials
__device__ float g_Xo[LQ * DM];            // out-proj result

// ---------------------------------------------------------------------------
// Generic NT SGEMM: C = alpha * A @ B^T (+ bias)
// ---------------------------------------------------------------------------
__global__ __launch_bounds__(256) void sgemm_nt(
    const float* __restrict__ A, int lda, int aStride,
    const float* __restrict__ B, int ldb, int bStride,
    float* __restrict__ C, int ldc, long cStride,
    int K, float alpha, const float* __restrict__ bias)
{
    __shared__ float As[8][132];
    __shared__ float Bs[8][132];

    const int bz = blockIdx.z;
    const float* Ab = A + (long)bz * aStride;
    const float* Bb = B + (long)bz * bStride;
    float* Cb = C + (long)bz * cStride;

    const int m0 = blockIdx.y * 128;
    const int n0 = blockIdx.x * 128;
    const int t  = threadIdx.x;
    const int tx = t & 15;
    const int ty = t >> 4;
    const int lrow = t >> 1;
    const int lk   = (t & 1) * 4;

    float acc[8][8];
#pragma unroll
    for (int i = 0; i < 8; i++)
#pragma unroll
        for (int j = 0; j < 8; j++) acc[i][j] = 0.0f;

    const float* aPtr = Ab + (long)(m0 + lrow) * lda + lk;
    const float* bPtr = Bb + (long)(n0 + lrow) * ldb + lk;

    for (int k0 = 0; k0 < K; k0 += 8) {
        float4 av = *(const float4*)(aPtr + k0);
        float4 bv = *(const float4*)(bPtr + k0);
        As[lk + 0][lrow] = av.x; As[lk + 1][lrow] = av.y;
        As[lk + 2][lrow] = av.z; As[lk + 3][lrow] = av.w;
        Bs[lk + 0][lrow] = bv.x; Bs[lk + 1][lrow] = bv.y;
        Bs[lk + 2][lrow] = bv.z; Bs[lk + 3][lrow] = bv.w;
        __syncthreads();

#pragma unroll
        for (int kk = 0; kk < 8; kk++) {
            float4 a0 = *(const float4*)&As[kk][ty * 8];
            float4 a1 = *(const float4*)&As[kk][ty * 8 + 4];
            float4 b0 = *(const float4*)&Bs[kk][tx * 8];
            float4 b1 = *(const float4*)&Bs[kk][tx * 8 + 4];
            float ar[8] = {a0.x, a0.y, a0.z, a0.w, a1.x, a1.y, a1.z, a1.w};
            float br_[8] = {b0.x, b0.y, b0.z, b0.w, b1.x, b1.y, b1.z, b1.w};
#pragma unroll
            for (int i = 0; i < 8; i++)
#pragma unroll
                for (int j = 0; j < 8; j++)
                    acc[i][j] = fmaf(ar[i], br_[j], acc[i][j]);
        }
        __syncthreads();
    }

    float bb[8];
#pragma unroll
    for (int j = 0; j < 8; j++) bb[j] = bias ? bias[n0 + tx * 8 + j] : 0.0f;

#pragma unroll
    for (int i = 0; i < 8; i++) {
        float* crow = Cb + (long)(m0 + ty * 8 + i) * ldc + n0 + tx * 8;
        float4 o0 = make_float4(fmaf(alpha, acc[i][0], bb[0]),
                                fmaf(alpha, acc[i][1], bb[1]),
                                fmaf(alpha, acc[i][2], bb[2]),
                                fmaf(alpha, acc[i][3], bb[3]));
        float4 o1 = make_float4(fmaf(alpha, acc[i][4], bb[4]),
                                fmaf(alpha, acc[i][5], bb[5]),
                                fmaf(alpha, acc[i][6], bb[6]),
                                fmaf(alpha, acc[i][7], bb[7]));
        *(float4*)crow       = o0;
        *(float4*)(crow + 4) = o1;
    }
}

// ---------------------------------------------------------------------------
// bias_exp_v2: one block per l. Double-buffered 128-p rbf tiles (dynamic smem),
// one barrier per tile. Warp w owns p-range [w*16, w*16+16); each row is
// handled by a lane PAIR (half=lane&1 takes r in [half*25, half*25+25)) ->
// smem address = 25*lane + r -> conflict-free. rbf read from smem exactly once.
// Wr held padded [h][half][32] so the weight operand is broadcast LDS.128.
// After shfl-combine, lane parity picks 4 heads -> all 32 lanes do S RW.
// ---------------------------------------------------------------------------
extern __shared__ float db_buf[];  // 2 * TPB * NR floats = 51.2 KB

__global__ __launch_bounds__(256) void bias_exp_v2(
    const float* __restrict__ rbf, const float* __restrict__ Wr,
    const float* __restrict__ br, float* __restrict__ S,
    float* __restrict__ rZ)
{
    __shared__ float wr_s[16 * 32];   // [h*2+half][32], zero-padded
    __shared__ float br_s[NH];
    __shared__ float zpart[8][NH];

    const int l    = blockIdx.x;
    const int t    = threadIdx.x;
    const int w    = t >> 5;
    const int lane = t & 31;
    const int row  = lane >> 1;
    const int half = lane & 1;

    for (int i = t; i < 16 * 32; i += 256) wr_s[i] = 0.0f;
    __syncthreads();
    for (int i = t; i < NH * NR; i += 256) {
        int h = i / NR, rr = i % NR;
        wr_s[(h * 2 + rr / 25) * 32 + (rr % 25)] = Wr[i];
    }
    if (t < NH) br_s[t] = br[t];

    const float* rbf_l = rbf + (long)l * PK * NR;
    float* buf0 = db_buf;
    float* buf1 = db_buf + TPB * NR;

    // prologue: tile 0
    {
        const float4* src = (const float4*)rbf_l;
        float4* dst = (float4*)buf0;
#pragma unroll 4
        for (int i = t; i < TPB * NR / 4; i += 256) dst[i] = src[i];
    }
    __syncthreads();   // also orders wr_s/br_s fills before first use

    float zacc[4] = {0.f, 0.f, 0.f, 0.f};
    const long lp = (long)l * PK;
    const int NT = PK / TPB;  // 32

    for (int tile = 0; tile < NT; tile++) {
        float* cur = (tile & 1) ? buf1 : buf0;
        float* nxt = (tile & 1) ? buf0 : buf1;

        if (tile + 1 < NT) {
            const float4* src = (const float4*)(rbf_l + (long)(tile + 1) * TPB * NR);
            float4* dst = (float4*)nxt;
#pragma unroll 4
            for (int i = t; i < TPB * NR / 4; i += 256) dst[i] = src[i];
        }

        // load 25 rbf values (this lane's half-row) into registers
        const float* rrow = cur + (w * 16 + row) * NR + half * 25;
        float rv[28];
#pragma unroll
        for (int r = 0; r < 25; r++) rv[r] = rrow[r];
        rv[25] = rv[26] = rv[27] = 0.0f;

        // 8 partial head dots over this half-row (vectorized weight loads)
        float acc[8];
#pragma unroll
        for (int h = 0; h < 8; h++) {
            const float4* wp = (const float4*)&wr_s[(h * 2 + half) * 32];
            float a0 = 0.f, a1 = 0.f, a2 = 0.f, a3 = 0.f;
#pragma unroll
            for (int q = 0; q < 7; q++) {
                float4 wv = wp[q];
                a0 = fmaf(rv[q * 4 + 0], wv.x, a0);
                a1 = fmaf(rv[q * 4 + 1], wv.y, a1);
                a2 = fmaf(rv[q * 4 + 2], wv.z, a2);
                a3 = fmaf(rv[q * 4 + 3], wv.w, a3);
            }
            acc[h] = (a0 + a1) + (a2 + a3);
        }

        // combine half-rows within the lane pair
#pragma unroll
        for (int h = 0; h < 8; h++)
            acc[h] += __shfl_xor_sync(0xFFFFFFFFu, acc[h], 1);

        // S read-modify-write: lane parity selects 4 heads; 16 same-parity
        // lanes cover 16 consecutive p -> 64B segments per head.
        const int p = tile * TPB + w * 16 + row;
#pragma unroll
        for (int j = 0; j < 4; j++) {
            const int h = half * 4 + j;
            float av = half ? acc[4 + j] : acc[j];
            float* ptr = S + (long)h * ((long)LQ * PK) + lp + p;
            float e = __expf(*ptr + av + br_s[h]);
            *ptr = e;
            zacc[j] += e;
        }

        __syncthreads();  // next-tile prefetch done AND cur free for overwrite
    }

    // reduce Z over same-parity lanes (covers all 16 rows of this warp)
#pragma unroll
    for (int j = 0; j < 4; j++) {
#pragma unroll
        for (int o = 2; o <= 16; o <<= 1)
            zacc[j] += __shfl_xor_sync(0xFFFFFFFFu, zacc[j], o);
    }
    if (lane < 2) {
#pragma unroll
        for (int j = 0; j < 4; j++) zpart[w][lane * 4 + j] = zacc[j];
    }
    __syncthreads();
    if (t < NH) {
        float s = 0.f;
#pragma unroll
        for (int ww = 0; ww < 8; ww++) s += zpart[ww][t];
        rZ[l * NH + t] = 1.0f / s;
    }
}

// ---------------------------------------------------------------------------
// attnv split-K: blockIdx.z = split s handles P-chunk [s*CHUNK, (s+1)*CHUNK).
// Unnormalized partials -> g_Op[s]. 128(l) x 64(d) tile, BK=16, 8x4 microtile.
// ---------------------------------------------------------------------------
__global__ __launch_bounds__(256) void attnv_split(
    const float* __restrict__ E, const float* __restrict__ V,
    float* __restrict__ Opart)
{
    __shared__ float As[16][132];
    __shared__ float Bs[16][64];

    const int h  = blockIdx.y;
    const int m0 = blockIdx.x * 128;
    const int sp = blockIdx.z;
    const float* Eh = E + (long)h * ((long)LQ * PK);

    const int t  = threadIdx.x;
    const int tx = t & 15;
    const int ty = t >> 4;
    const int arow = t >> 1;
    const int ak   = (t & 1) * 8;
    const int bk   = t >> 4;
    const int bf   = t & 15;

    float acc[8][4];
#pragma unroll
    for (int i = 0; i < 8; i++)
#pragma unroll
        for (int j = 0; j < 4; j++) acc[i][j] = 0.0f;

    const float* aPtr = Eh + (long)(m0 + arow) * PK + sp * CHUNK + ak;
    const float* bPtr = V + (long)(sp * CHUNK + bk) * DM + h * DH + bf * 4;

    for (int k0 = 0; k0 < CHUNK; k0 += 16) {
        float4 a0 = *(const float4*)(aPtr + k0);
        float4 a1 = *(const float4*)(aPtr + k0 + 4);
        float4 bv = *(const float4*)(bPtr + (long)k0 * DM);
        As[ak + 0][arow] = a0.x; As[ak + 1][arow] = a0.y;
        As[ak + 2][arow] = a0.z; As[ak + 3][arow] = a0.w;
        As[ak + 4][arow] = a1.x; As[ak + 5][arow] = a1.y;
        As[ak + 6][arow] = a1.z; As[ak + 7][arow] = a1.w;
        *(float4*)&Bs[bk][bf * 4] = bv;
        __syncthreads();

#pragma unroll
        for (int kk = 0; kk < 16; kk++) {
            float4 a0v = *(const float4*)&As[kk][ty * 8];
            float4 a1v = *(const float4*)&As[kk][ty * 8 + 4];
            float4 b   = *(const float4*)&Bs[kk][tx * 4];
            float ar[8] = {a0v.x, a0v.y, a0v.z, a0v.w, a1v.x, a1v.y, a1v.z, a1v.w};
            float br_[4] = {b.x, b.y, b.z, b.w};
#pragma unroll
            for (int i = 0; i < 8; i++)
#pragma unroll
                for (int j = 0; j < 4; j++)
                    acc[i][j] = fmaf(ar[i], br_[j], acc[i][j]);
        }
        __syncthreads();
    }

    float* Ob = Opart + (long)sp * ((long)LQ * DM);
#pragma unroll
    for (int i = 0; i < 8; i++) {
        int m = m0 + ty * 8 + i;
        float4 o = make_float4(acc[i][0], acc[i][1], acc[i][2], acc[i][3]);
        *(float4*)(Ob + (long)m * DM + h * DH + tx * 4) = o;
    }
}

// ---------------------------------------------------------------------------
// reduce split-K partials + apply 1/Z: O[l,d] = rZ[l, d/DH] * sum_s Op[s][l,d]
// ---------------------------------------------------------------------------
__global__ __launch_bounds__(256) void attnv_reduce(
    const float* __restrict__ Opart, const float* __restrict__ rZ,
    float* __restrict__ O)
{
    const int idx = blockIdx.x * 256 + threadIdx.x;  // float4 index
    const int l  = idx / (DM / 4);
    const int d4 = idx % (DM / 4);
    const int h  = d4 / (DH / 4);

    float4 s = make_float4(0.f, 0.f, 0.f, 0.f);
#pragma unroll
    for (int sp = 0; sp < SPLIT; sp++) {
        float4 v = *(const float4*)(Opart + (long)sp * ((long)LQ * DM) + (long)idx * 4);
        s.x += v.x; s.y += v.y; s.z += v.z; s.w += v.w;
    }
    const float sc = rZ[l * NH + h];
    s.x *= sc; s.y *= sc; s.z *= sc; s.w *= sc;
    *(float4*)(O + (long)idx * 4) = s;
}

// ---------------------------------------------------------------------------
// attn_mean[l,p] = (1/8) * sum_h E[h][l][p] * rZ[l,h]
// ---------------------------------------------------------------------------
__global__ __launch_bounds__(256) void attn_mean_kernel(
    const float* __restrict__ E, const float* __restrict__ rZ,
    float* __restrict__ out)
{
    __shared__ float rz[NH];
    const int l = blockIdx.x >> 4;
    const int p = ((blockIdx.x & 15) << 8) + threadIdx.x;
    if (threadIdx.x < NH) rz[threadIdx.x] = rZ[l * NH + threadIdx.x];
    __syncthreads();

    const float* El = E + (long)l * PK + p;
    float s = 0.0f;
#pragma unroll
    for (int h = 0; h < NH; h++)
        s = fmaf(El[(long)h * ((long)LQ * PK)], rz[h], s);
    out[(long)l * PK + p] = s * 0.125f;
}

// ---------------------------------------------------------------------------
// LayerNorm(query + Xo) * gamma + beta
// ---------------------------------------------------------------------------
__global__ __launch_bounds__(256) void ln_kernel(
    const float* __restrict__ query, const float* __restrict__ Xo,
    const float* __restrict__ gamma, const float* __restrict__ beta,
    float* __restrict__ y)
{
    __shared__ float rs[8], rq[8];
    const int l = blockIdx.x;
    const int t = threadIdx.x;
    const int lane = t & 31, warp = t >> 5;

    float2 q  = *(const float2*)(query + (long)l * DM + t * 2);
    float2 xo = *(const float2*)(Xo    + (long)l * DM + t * 2);
    float x0 = q.x + xo.x;
    float x1 = q.y + xo.y;

    float s  = x0 + x1;
    float sq = x0 * x0 + x1 * x1;
#pragma unroll
    for (int o = 16; o > 0; o >>= 1) {
        s  += __shfl_xor_sync(0xFFFFFFFFu, s, o);
        sq += __shfl_xor_sync(0xFFFFFFFFu, sq, o);
    }
    if (lane == 0) { rs[warp] = s; rq[warp] = sq; }
    __syncthreads();
    if (warp == 0) {
        float a = (lane < 8) ? rs[lane] : 0.0f;
        float b = (lane < 8) ? rq[lane] : 0.0f;
#pragma unroll
        for (int o = 4; o > 0; o >>= 1) {
            a += __shfl_xor_sync(0xFFFFFFFFu, a, o);
            b += __shfl_xor_sync(0xFFFFFFFFu, b, o);
        }
        if (lane == 0) { rs[0] = a; rq[0] = b; }
    }
    __syncthreads();

    const float mean = rs[0] * (1.0f / DM);
    const float var  = rq[0] * (1.0f / DM) - mean * mean;
    const float rstd = rsqrtf(var + 1e-5f);

    float2 g = *(const float2*)(gamma + t * 2);
    float2 b = *(const float2*)(beta + t * 2);
    float2 o;
    o.x = (x0 - mean) * rstd * g.x + b.x;
    o.y = (x1 - mean) * rstd * g.y + b.y;
    *(float2*)(y + (long)l * DM + t * 2) = o;
}

// ---------------------------------------------------------------------------
extern "C" void kernel_launch(void* const* d_in, const int* in_sizes, int n_in,
                              void* d_out, int out_size)
{
    const float* query = (const float*)d_in[0];
    const float* key   = (const float*)d_in[1];
    const float* value = (const float*)d_in[2];
    const float* rbf   = (const float*)d_in[3];
    const float* Wq = (const float*)d_in[4];
    const float* bq = (const float*)d_in[5];
    const float* Wk = (const float*)d_in[6];
    const float* bk = (const float*)d_in[7];
    const float* Wv = (const float*)d_in[8];
    const float* bv = (const float*)d_in[9];
    const float* Wr = (const float*)d_in[10];
    const float* br = (const float*)d_in[11];
    const float* Wo = (const float*)d_in[12];
    const float* bo = (const float*)d_in[13];
    const float* gamma = (const float*)d_in[14];
    const float* beta  = (const float*)d_in[15];
    float* out = (float*)d_out;

    float *Qp, *Kp, *Vp, *S, *rZ, *O, *Op, *Xo;
    cudaGetSymbolAddress((void**)&Qp, g_Qp);
    cudaGetSymbolAddress((void**)&Kp, g_Kp);
    cudaGetSymbolAddress((void**)&Vp, g_Vp);
    cudaGetSymbolAddress((void**)&S,  g_S);
    cudaGetSymbolAddress((void**)&rZ, g_rZ);
    cudaGetSymbolAddress((void**)&O,  g_O);
    cudaGetSymbolAddress((void**)&Op, g_Op);
    cudaGetSymbolAddress((void**)&Xo, g_Xo);

    const int dynsmem = 2 * TPB * NR * sizeof(float);  // 51.2 KB
    cudaFuncSetAttribute(bias_exp_v2, cudaFuncAttributeMaxDynamicSharedMemorySize,
                         dynsmem);

    // Projections: X @ W^T + b  (NT gemm, K=512)
    sgemm_nt<<<dim3(DM / 128, LQ / 128, 1), 256>>>(query, DM, 0, Wq, DM, 0,
                                                   Qp, DM, 0, DM, 1.0f, bq);
    sgemm_nt<<<dim3(DM / 128, PK / 128, 1), 256>>>(key, DM, 0, Wk, DM, 0,
                                                   Kp, DM, 0, DM, 1.0f, bk);
    sgemm_nt<<<dim3(DM / 128, PK / 128, 1), 256>>>(value, DM, 0, Wv, DM, 0,
                                                   Vp, DM, 0, DM, 1.0f, bv);

    // Scores: per head, S[h][l][p] = 0.125 * Q_h[l,:] . K_h[p,:]
    sgemm_nt<<<dim3(PK / 128, LQ / 128, NH), 256>>>(Qp, DM, DH, Kp, DM, DH,
                                                    S, PK, (long)LQ * PK,
                                                    DH, 0.125f, nullptr);

    // bias from cross_rbf + exp + per-(l,h) denominator
    bias_exp_v2<<<LQ, 256, dynsmem>>>(rbf, Wr, br, S, rZ);

    // attn @ V, split-K, then reduce + 1/Z
    attnv_split<<<dim3(LQ / 128, NH, SPLIT), 256>>>(S, Vp, Op);
    attnv_reduce<<<(LQ * DM / 4) / 256, 256>>>(Op, rZ, O);

    // attn.mean over heads -> second output
    attn_mean_kernel<<<LQ * (PK / 256), 256>>>(S, rZ, out + (long)LQ * DM);

    // output projection
    sgemm_nt<<<dim3(DM / 128, LQ / 128, 1), 256>>>(O, DM, 0, Wo, DM, 0,
                                                   Xo, DM, 0, DM, 1.0f, bo);

    // residual + layernorm -> first output
    ln_kernel<<<LQ, 256>>>(query, Xo, gamma, beta, out);
}